// round 1
// baseline (speedup 1.0000x reference)
#include <cuda_runtime.h>
#include <math.h>
#include <stdint.h>

// Problem constants (fixed shapes per reference)
#define BB 32
#define PP 16384
#define TT 64
#define NC 32                 // pred chunks per batch
#define CP (PP / NC)          // 512 preds per chunk
#define NSUB 16               // pred sub-streams per block
#define NT 8                  // targets per thread
#define TPB 128               // threads per block (NSUB * (TT/NT))
#define PPT (CP / NSUB)       // 32 preds per thread

// Scratch (no allocations allowed)
__device__ float g_part_iou[BB * NC * TT];
__device__ int   g_part_idx[BB * NC * TT];
__device__ float g_conf_part[BB * NC];
__device__ float g_per[BB];

__device__ __forceinline__ float softplus_f(float x) {
    // stable softplus; logits here are in [0,1) but keep the stable form
    return fmaxf(x, 0.0f) + log1pf(expf(-fabsf(x)));
}

// Kernel 1: per (batch, chunk): for all 64 targets find local (max iou, min idx)
// over this chunk's 512 preds; also partial sum of softplus(logit) for conf loss.
__global__ void __launch_bounds__(TPB) iou_kernel(
    const float* __restrict__ preds, const float* __restrict__ targets)
{
    const int c = blockIdx.x;
    const int b = blockIdx.y;
    const int tid = threadIdx.x;
    const int tg  = tid >> 4;    // 0..7  -> targets tg*8 .. tg*8+7
    const int sub = tid & 15;    // 0..15 -> pred sub-stream

    // Load this thread's 8 targets into registers
    float gx1[NT], gy1[NT], gx2[NT], gy2[NT], ga[NT];
    const float* tb = targets + (size_t)b * TT * 4;
    #pragma unroll
    for (int k = 0; k < NT; k++) {
        int t = tg * NT + k;
        float x = __ldg(tb + t * 4 + 0);
        float y = __ldg(tb + t * 4 + 1);
        float w = __ldg(tb + t * 4 + 2);
        float h = __ldg(tb + t * 4 + 3);
        gx1[k] = x; gy1[k] = y; gx2[k] = x + w; gy2[k] = y + h; ga[k] = w * h;
    }

    float biou[NT];
    int   bidx[NT];
    #pragma unroll
    for (int k = 0; k < NT; k++) { biou[k] = -1.0f; bidx[k] = 0x7fffffff; }

    const float* pbase = preds + (size_t)b * PP * 5;
    const int p0 = c * CP + sub;

    #pragma unroll 2
    for (int i = 0; i < PPT; i++) {
        const int p = p0 + i * NSUB;
        const float* pr = pbase + (size_t)p * 5;
        float px1 = __ldg(pr + 0);
        float py1 = __ldg(pr + 1);
        float pw  = __ldg(pr + 2);
        float ph  = __ldg(pr + 3);
        float px2 = px1 + pw, py2 = py1 + ph, pa = pw * ph;
        #pragma unroll
        for (int k = 0; k < NT; k++) {
            float xa = fmaxf(gx1[k], px1);
            float xb = fminf(gx2[k], px2);
            float ya = fmaxf(gy1[k], py1);
            float yb = fminf(gy2[k], py2);
            float w  = fmaxf(xb - xa, 0.0f);
            float h  = fmaxf(yb - ya, 0.0f);
            float inter = w * h;
            float u = pa + ga[k] - inter;
            float iou = __fdividef(inter, fmaxf(u, 1e-12f));
            if (iou > biou[k]) { biou[k] = iou; bidx[k] = p; }
        }
    }

    // Reduce across the 16 sub-streams per target (tie-break: min idx on equal iou)
    __shared__ float s_iou[TT][NSUB + 1];
    __shared__ int   s_idx[TT][NSUB + 1];
    #pragma unroll
    for (int k = 0; k < NT; k++) {
        s_iou[tg * NT + k][sub] = biou[k];
        s_idx[tg * NT + k][sub] = bidx[k];
    }
    __syncthreads();
    if (tid < TT) {
        float bi = -1.0f; int bx = 0x7fffffff;
        #pragma unroll
        for (int s = 0; s < NSUB; s++) {
            float v = s_iou[tid][s]; int id = s_idx[tid][s];
            if (v > bi || (v == bi && id < bx)) { bi = v; bx = id; }
        }
        g_part_iou[(b * NC + c) * TT + tid] = bi;
        g_part_idx[(b * NC + c) * TT + tid] = bx;
    }

    // Conf partial: sum softplus(logit) over this chunk's 512 logits
    float acc = 0.0f;
    for (int i = tid; i < CP; i += TPB) {
        float l = __ldg(pbase + (size_t)(c * CP + i) * 5 + 4);
        acc += softplus_f(l);
    }
    __shared__ float s_red[TPB];
    s_red[tid] = acc;
    __syncthreads();
    for (int s = TPB / 2; s > 0; s >>= 1) {
        if (tid < s) s_red[tid] += s_red[tid + s];
        __syncthreads();
    }
    if (tid == 0) g_conf_part[b * NC + c] = s_red[0];
}

// Kernel 2: one block per batch (64 threads = one per target).
// Reduce chunk partials -> (biou, best); build unique sorted positive set;
// compute bbox loss + conf loss -> g_per[b].
__global__ void __launch_bounds__(TT) finalize_kernel(
    const float* __restrict__ preds, const float* __restrict__ targets)
{
    const int b = blockIdx.x;
    const int t = threadIdx.x;

    float bi = -1.0f; int bx = 0x7fffffff;
    for (int c = 0; c < NC; c++) {
        float v = g_part_iou[(b * NC + c) * TT + t];
        int  id = g_part_idx[(b * NC + c) * TT + t];
        if (v > bi || (v == bi && id < bx)) { bi = v; bx = id; }
    }
    // flag = biou > 0.5 ; positive candidate index or sentinel
    int val = (bi > 0.5f) ? bx : 0x7fffffff;

    __shared__ int vals[TT];
    vals[t] = val;
    __syncthreads();
    // dedupe: keep only the lowest-t occurrence of each value
    bool dup = false;
    if (val != 0x7fffffff) {
        for (int j = 0; j < t; j++) dup |= (vals[j] == val);
    }
    if (dup) val = 0x7fffffff;
    __syncthreads();
    vals[t] = val;
    __syncthreads();

    // rank-sort ascending (sentinels go last; ties among sentinels broken by t)
    int rank = 0;
    for (int j = 0; j < TT; j++) {
        int vj = vals[j];
        rank += (vj < val) || (vj == val && j < t);
    }
    __shared__ int sorted_[TT];
    sorted_[rank] = val;
    int n = __syncthreads_count(val != 0x7fffffff);  // also the barrier for sorted_

    float sq = 0.0f, corr = 0.0f;
    if (t < n) {
        int p = sorted_[t];
        const float* pp = preds + ((size_t)b * PP + p) * 5;
        const float* tg = targets + ((size_t)b * TT + t) * 4;
        #pragma unroll
        for (int k = 0; k < 4; k++) {
            float d = __ldg(pp + k) - __ldg(tg + k);
            sq += d * d;
        }
        // positive conf correction: softplus(-l) - softplus(l) == -l exactly
        corr = -__ldg(pp + 4);
    }
    float base = (t < NC) ? g_conf_part[b * NC + t] : 0.0f;

    __shared__ float sr[TT], sr2[TT], sr3[TT];
    sr[t] = sq; sr2[t] = corr; sr3[t] = base;
    __syncthreads();
    for (int s = TT / 2; s > 0; s >>= 1) {
        if (t < s) { sr[t] += sr[t + s]; sr2[t] += sr2[t + s]; sr3[t] += sr3[t + s]; }
        __syncthreads();
    }
    if (t == 0) {
        float conf = (sr3[0] + sr2[0]) * (1.0f / (float)PP);
        float bbox = sr[0] / fmaxf((float)n * 4.0f, 1.0f);
        g_per[b] = (n > 0) ? (bbox + conf) : 0.0f;
    }
}

// Kernel 3: sum per-image losses / B
__global__ void sum_kernel(float* __restrict__ out)
{
    int t = threadIdx.x;  // 32 threads
    float v = g_per[t];
    #pragma unroll
    for (int o = 16; o > 0; o >>= 1) v += __shfl_down_sync(0xffffffffu, v, o);
    if (t == 0) out[0] = v * (1.0f / (float)BB);
}

extern "C" void kernel_launch(void* const* d_in, const int* in_sizes, int n_in,
                              void* d_out, int out_size)
{
    const float* preds   = (const float*)d_in[0];
    const float* targets = (const float*)d_in[1];
    float* out = (float*)d_out;

    iou_kernel<<<dim3(NC, BB), TPB>>>(preds, targets);
    finalize_kernel<<<BB, TT>>>(preds, targets);
    sum_kernel<<<1, 32>>>(out);
}